// round 16
// baseline (speedup 1.0000x reference)
#include <cuda_runtime.h>

#define FH 128
#define FO 64
#define NMAX 50048
#define EMAX 800000
#define SCAN_B 1024
#define NBLK ((NMAX + SCAN_B - 1) / SCAN_B)   // 49

// ---------------- scratch (device globals: no allocation allowed) ------------
__device__ float g_H1[(size_t)NMAX * FH];   // x @ W1
__device__ float g_HG2[(size_t)NMAX * FO];  // bnrelu(hidden) @ W2
__device__ float g_dinv1[NMAX];
__device__ float g_dinv2[NMAX];
__device__ int   g_cnt1[NMAX];
__device__ int   g_cnt2[NMAX];
__device__ int   g_off1[NMAX + 1];  // [i]: local exclusive prefix; [N]: final total
__device__ int   g_off2[NMAX + 1];
__device__ int   g_pos1[NMAX];
__device__ int   g_pos2[NMAX];
__device__ int   g_csr1[EMAX];
__device__ int   g_csr2[EMAX];
__device__ int   g_bsum[2][NBLK];   // after scanA: exclusive block bases
__device__ float g_sum[FH];
__device__ float g_sumsq[FH];
__device__ float g_scale[FH];
__device__ float g_shift[FH];
__device__ int   g_doneA;
__device__ int   g_done1;

// ---------------- packed f32x2 helpers (sm_100+) ------------------------------
__device__ __forceinline__ unsigned long long pack2(float lo, float hi) {
    unsigned long long r;
    asm("mov.b64 %0, {%1, %2};" : "=l"(r) : "f"(lo), "f"(hi));
    return r;
}
__device__ __forceinline__ void fma2(unsigned long long& d, unsigned long long a,
                                     unsigned long long b) {
    asm("fma.rn.f32x2 %0, %1, %2, %0;" : "+l"(d) : "l"(a), "l"(b));
}
__device__ __forceinline__ void unpack2(unsigned long long u, float& lo, float& hi) {
    asm("mov.b64 {%0, %1}, %2;" : "=f"(lo), "=f"(hi) : "l"(u));
}

// ---------------- zero counters ------------------------------------------------
__global__ void zero_kernel(int N) {
    int i = blockIdx.x * blockDim.x + threadIdx.x;
    if (i < N) { g_cnt1[i] = 0; g_cnt2[i] = 0; g_pos1[i] = 0; g_pos2[i] = 0; }
    if (i < FH) { g_sum[i] = 0.f; g_sumsq[i] = 0.f; }
    if (i == 0) { g_doneA = 0; g_done1 = 0; }
}

// ---------------- degree count (dst side, both graphs) -------------------------
__global__ void deg_kernel(const int* __restrict__ e1,
                           const int* __restrict__ e2, int E) {
    int i = blockIdx.x * blockDim.x + threadIdx.x;
    if (i < E) {
        atomicAdd(&g_cnt1[e1[E + i]], 1);
        atomicAdd(&g_cnt2[e2[E + i]], 1);
    }
}

// ---------------- scan A: per-block scan + totals + dinv; last block scans totals
__global__ void __launch_bounds__(SCAN_B) scanA_kernel(int N) {
    const int* cnt  = blockIdx.y ? g_cnt2  : g_cnt1;
    int*       off  = blockIdx.y ? g_off2  : g_off1;
    float*     dinv = blockIdx.y ? g_dinv2 : g_dinv1;
    __shared__ int sh[SCAN_B];
    __shared__ int isLast;
    int t = threadIdx.x;
    int i = blockIdx.x * SCAN_B + t;
    int v = (i < N) ? cnt[i] : 0;
    if (i < N) dinv[i] = rsqrtf((float)v + 1.0f);  // +1 = self loop
    sh[t] = v;
    __syncthreads();
#pragma unroll
    for (int d = 1; d < SCAN_B; d <<= 1) {
        int u = (t >= d) ? sh[t - d] : 0;
        __syncthreads();
        sh[t] += u;
        __syncthreads();
    }
    if (i < N) off[i] = sh[t] - v;  // block-local exclusive prefix
    if (t == SCAN_B - 1) g_bsum[blockIdx.y][blockIdx.x] = sh[t];

    // ---- fused phase B: last block scans the per-block totals -> bases ----
    __threadfence();
    __syncthreads();
    if (t == 0)
        isLast = (atomicAdd(&g_doneA, 1) == (int)(gridDim.x * gridDim.y) - 1);
    __syncthreads();
    if (!isLast) return;
    int nbv = gridDim.x;
    int g = t >> 6, j = t & 63;  // 128 threads active, 64 per graph
    int bv = 0;
    if (t < 128) { bv = (j < nbv) ? g_bsum[g][j] : 0; sh[t] = bv; }
    __syncthreads();
#pragma unroll
    for (int d = 1; d < 64; d <<= 1) {
        int u = 0;
        if (t < 128 && j >= d) u = sh[t - d];
        __syncthreads();
        if (t < 128) sh[t] += u;
        __syncthreads();
    }
    if (t < 128 && j < nbv) g_bsum[g][j] = sh[t] - bv;  // exclusive bases
    if (t < 128 && j == 63) {
        if (g == 0) g_off1[N] = sh[t]; else g_off2[N] = sh[t];
    }
}

// final offset helpers (off[] is block-local; bsum holds bases)
__device__ __forceinline__ int off1_final(int i) {
    return g_off1[i] + g_bsum[0][i >> 10];
}
__device__ __forceinline__ int off2_final(int i) {
    return g_off2[i] + g_bsum[1][i >> 10];
}

// ---------------- merged GEMM1 (f32x2, 128x128 tile) + CSR fill ----------------
// Blocks [0, gm): g_H1 = X @ W1 (BM=128, BN=128, BK=32, 8x8/thread, FFMA2).
// Blocks [gm, ..): CSR fill for both graphs (adds scan bases inline).
__global__ void __launch_bounds__(256)
gemm1_fill_kernel(const float* __restrict__ X, const float* __restrict__ W,
                  int N, const int* __restrict__ e1, const int* __restrict__ e2,
                  int E, int gm) {
    __shared__ float XsT[32][132];
    __shared__ float Ws[32][132];
    const int tid = threadIdx.x;

    if ((int)blockIdx.x >= gm) {
        // ---- CSR fill part ----
        int i = (blockIdx.x - gm) * 256 + tid;
        if (i < E) {
            int s = e1[i], d = e1[E + i];
            int slot = atomicAdd(&g_pos1[d], 1);
            g_csr1[off1_final(d) + slot] = s;
        } else if (i < 2 * E) {
            int j = i - E;
            int s = e2[j], d = e2[E + j];
            int slot = atomicAdd(&g_pos2[d], 1);
            g_csr2[off2_final(d) + slot] = s;
        }
        return;
    }

    // ---- GEMM part: 128 rows x 128 cols per block ----
    const int row0 = blockIdx.x * 128;
    const int tx   = tid & 15;   // 16 col groups: cols tx*4..+3 and 64+tx*4..+3
    const int ty   = tid >> 4;   // 16 row groups: rows ty*8..+7

    unsigned long long acc[4][8];  // [M row-pair][col], f32x2 {row 2p, 2p+1}
#pragma unroll
    for (int p = 0; p < 4; p++)
#pragma unroll
        for (int j = 0; j < 8; j++) acc[p][j] = 0ull;

    for (int kc = 0; kc < FH; kc += 32) {
        __syncthreads();
        // X tile: 128 rows x 32 k, transposed store (k-major)
        for (int i = tid; i < 1024; i += 256) {
            int r = i >> 3, c4 = i & 7;
            int row = row0 + r;
            float4 v = make_float4(0.f, 0.f, 0.f, 0.f);
            if (row < N)
                v = reinterpret_cast<const float4*>(X + (size_t)row * FH + kc)[c4];
            int k0 = c4 * 4;
            XsT[k0 + 0][r] = v.x;
            XsT[k0 + 1][r] = v.y;
            XsT[k0 + 2][r] = v.z;
            XsT[k0 + 3][r] = v.w;
        }
        // W tile: 32 k x 128 cols
        for (int i = tid; i < 1024; i += 256) {
            int k = i >> 5, c4 = i & 31;
            *reinterpret_cast<float4*>(&Ws[k][c4 * 4]) =
                reinterpret_cast<const float4*>(W + (size_t)(kc + k) * FH)[c4];
        }
        __syncthreads();

#pragma unroll
        for (int k = 0; k < 32; ++k) {
            union { float4 f; unsigned long long u[2]; } A0, A1;
            A0.f = *reinterpret_cast<const float4*>(&XsT[k][ty * 8]);      // broadcast
            A1.f = *reinterpret_cast<const float4*>(&XsT[k][ty * 8 + 4]);
            unsigned long long av[4] = {A0.u[0], A0.u[1], A1.u[0], A1.u[1]};
            float4 b0 = *reinterpret_cast<const float4*>(&Ws[k][tx * 4]);       // cf-free
            float4 b1 = *reinterpret_cast<const float4*>(&Ws[k][64 + tx * 4]);  // cf-free
            unsigned long long bd[8] = {
                pack2(b0.x, b0.x), pack2(b0.y, b0.y), pack2(b0.z, b0.z), pack2(b0.w, b0.w),
                pack2(b1.x, b1.x), pack2(b1.y, b1.y), pack2(b1.z, b1.z), pack2(b1.w, b1.w)};
#pragma unroll
            for (int p = 0; p < 4; p++)
#pragma unroll
                for (int j = 0; j < 8; j++) fma2(acc[p][j], av[p], bd[j]);
        }
    }

#pragma unroll
    for (int p = 0; p < 4; p++) {
        int r0 = row0 + ty * 8 + 2 * p;
        float lo[8], hi[8];
#pragma unroll
        for (int j = 0; j < 8; j++) unpack2(acc[p][j], lo[j], hi[j]);
        if (r0 < N) {
            *reinterpret_cast<float4*>(&g_H1[(size_t)r0 * FH + tx * 4]) =
                make_float4(lo[0], lo[1], lo[2], lo[3]);
            *reinterpret_cast<float4*>(&g_H1[(size_t)r0 * FH + 64 + tx * 4]) =
                make_float4(lo[4], lo[5], lo[6], lo[7]);
        }
        if (r0 + 1 < N) {
            *reinterpret_cast<float4*>(&g_H1[(size_t)(r0 + 1) * FH + tx * 4]) =
                make_float4(hi[0], hi[1], hi[2], hi[3]);
            *reinterpret_cast<float4*>(&g_H1[(size_t)(r0 + 1) * FH + 64 + tx * 4]) =
                make_float4(hi[4], hi[5], hi[6], hi[7]);
        }
    }
}

// ---------------- GEMM2 (f32x2): g_HG2 = bnrelu(hidden) @ W2 -------------------
__global__ void __launch_bounds__(256)
gemm2_kernel(const float* __restrict__ X, const float* __restrict__ W, int N) {
    __shared__ float XsT[32][132];
    __shared__ float Ws[32][68];

    const int row0 = blockIdx.x * 128;
    const int tid  = threadIdx.x;
    const int tx   = tid & 15;
    const int ty   = tid >> 4;

    unsigned long long acc[4][4];
#pragma unroll
    for (int p = 0; p < 4; p++)
#pragma unroll
        for (int j = 0; j < 4; j++) acc[p][j] = 0ull;

    for (int kc = 0; kc < FH; kc += 32) {
        __syncthreads();
        for (int i = tid; i < 1024; i += 256) {
            int r = i >> 3, c4 = i & 7;
            int row = row0 + r;
            float4 v = make_float4(0.f, 0.f, 0.f, 0.f);
            if (row < N)
                v = reinterpret_cast<const float4*>(X + (size_t)row * FH + kc)[c4];
            int k0 = c4 * 4;
            int g = kc + k0;
            v.x = fmaxf(fmaf(v.x, g_scale[g + 0], g_shift[g + 0]), 0.f);
            v.y = fmaxf(fmaf(v.y, g_scale[g + 1], g_shift[g + 1]), 0.f);
            v.z = fmaxf(fmaf(v.z, g_scale[g + 2], g_shift[g + 2]), 0.f);
            v.w = fmaxf(fmaf(v.w, g_scale[g + 3], g_shift[g + 3]), 0.f);
            XsT[k0 + 0][r] = v.x;
            XsT[k0 + 1][r] = v.y;
            XsT[k0 + 2][r] = v.z;
            XsT[k0 + 3][r] = v.w;
        }
        for (int i = tid; i < 512; i += 256) {
            int k = i >> 4, c4 = i & 15;
            reinterpret_cast<float4*>(&Ws[k][0])[c4] =
                reinterpret_cast<const float4*>(W + (size_t)(kc + k) * FO)[c4];
        }
        __syncthreads();

#pragma unroll
        for (int k = 0; k < 32; ++k) {
            union { float4 f; unsigned long long u[2]; } A0, A1;
            A0.f = *reinterpret_cast<const float4*>(&XsT[k][ty * 8]);
            A1.f = *reinterpret_cast<const float4*>(&XsT[k][ty * 8 + 4]);
            unsigned long long av[4] = {A0.u[0], A0.u[1], A1.u[0], A1.u[1]};
            float4 b = *reinterpret_cast<const float4*>(&Ws[k][tx * 4]);
            unsigned long long bd[4] = {pack2(b.x, b.x), pack2(b.y, b.y),
                                        pack2(b.z, b.z), pack2(b.w, b.w)};
#pragma unroll
            for (int p = 0; p < 4; p++)
#pragma unroll
                for (int j = 0; j < 4; j++) fma2(acc[p][j], av[p], bd[j]);
        }
    }

#pragma unroll
    for (int p = 0; p < 4; p++) {
        int r0 = row0 + ty * 8 + 2 * p;
        float lo[4], hi[4];
#pragma unroll
        for (int j = 0; j < 4; j++) unpack2(acc[p][j], lo[j], hi[j]);
        if (r0 < N)
            *reinterpret_cast<float4*>(&g_HG2[(size_t)r0 * FO + tx * 4]) =
                make_float4(lo[0], lo[1], lo[2], lo[3]);
        if (r0 + 1 < N)
            *reinterpret_cast<float4*>(&g_HG2[(size_t)(r0 + 1) * FO + tx * 4]) =
                make_float4(hi[0], hi[1], hi[2], hi[3]);
    }
}

// ---------------- gather layer 1 (fused bias+selfloop+BN stats+BN prep) --------
__global__ void __launch_bounds__(256)
gather1_kernel(const float* __restrict__ b1, const float* __restrict__ gamma,
               const float* __restrict__ beta, float* __restrict__ hidden,
               int N, float invN) {
    __shared__ float s_s[FH], s_q[FH];
    __shared__ int isLast;
    int tid = threadIdx.x;
    if (tid < FH) { s_s[tid] = 0.f; s_q[tid] = 0.f; }
    __syncthreads();

    int node = blockIdx.x * 8 + (tid >> 5);
    int lane = tid & 31;
    if (node < N) {
        int beg = off1_final(node);
        int nxt = node + 1;
        int end = (nxt == N) ? g_off1[N] : off1_final(nxt);
        float4 acc = make_float4(0.f, 0.f, 0.f, 0.f);
        const float4* H = reinterpret_cast<const float4*>(g_H1);
        int j = beg;
        for (; j + 4 <= end; j += 4) {
            int s0 = g_csr1[j], s1 = g_csr1[j + 1];
            int s2 = g_csr1[j + 2], s3 = g_csr1[j + 3];
            float w0 = g_dinv1[s0], w1 = g_dinv1[s1];
            float w2 = g_dinv1[s2], w3 = g_dinv1[s3];
            float4 v0 = H[(size_t)s0 * 32 + lane];
            float4 v1 = H[(size_t)s1 * 32 + lane];
            float4 v2 = H[(size_t)s2 * 32 + lane];
            float4 v3 = H[(size_t)s3 * 32 + lane];
            acc.x += w0 * v0.x + w1 * v1.x + w2 * v2.x + w3 * v3.x;
            acc.y += w0 * v0.y + w1 * v1.y + w2 * v2.y + w3 * v3.y;
            acc.z += w0 * v0.z + w1 * v1.z + w2 * v2.z + w3 * v3.z;
            acc.w += w0 * v0.w + w1 * v1.w + w2 * v2.w + w3 * v3.w;
        }
        for (; j < end; ++j) {
            int s = g_csr1[j];
            float w = g_dinv1[s];
            float4 v = H[(size_t)s * 32 + lane];
            acc.x += w * v.x; acc.y += w * v.y;
            acc.z += w * v.z; acc.w += w * v.w;
        }
        float di = g_dinv1[node];
        float4 h  = H[(size_t)node * 32 + lane];
        float4 bb = reinterpret_cast<const float4*>(b1)[lane];
        float4 v;
        v.x = di * acc.x + di * di * h.x + bb.x;
        v.y = di * acc.y + di * di * h.y + bb.y;
        v.z = di * acc.z + di * di * h.z + bb.z;
        v.w = di * acc.w + di * di * h.w + bb.w;
        reinterpret_cast<float4*>(hidden)[(size_t)node * 32 + lane] = v;
        int f = lane * 4;
        atomicAdd(&s_s[f + 0], v.x); atomicAdd(&s_q[f + 0], v.x * v.x);
        atomicAdd(&s_s[f + 1], v.y); atomicAdd(&s_q[f + 1], v.y * v.y);
        atomicAdd(&s_s[f + 2], v.z); atomicAdd(&s_q[f + 2], v.z * v.z);
        atomicAdd(&s_s[f + 3], v.w); atomicAdd(&s_q[f + 3], v.w * v.w);
    }
    __syncthreads();
    if (tid < FH) {
        atomicAdd(&g_sum[tid], s_s[tid]);
        atomicAdd(&g_sumsq[tid], s_q[tid]);
    }
    __threadfence();
    __syncthreads();
    if (tid == 0) isLast = (atomicAdd(&g_done1, 1) == (int)gridDim.x - 1);
    __syncthreads();
    if (isLast && tid < FH) {  // fused BN scale/shift
        float mean = g_sum[tid] * invN;
        float var  = g_sumsq[tid] * invN - mean * mean;
        float sc = gamma[tid] * rsqrtf(var + 1e-5f);
        g_scale[tid] = sc;
        g_shift[tid] = beta[tid] - mean * sc;
    }
}

// ---------------- gather layer 2 (warp/node, float2 lanes, fused epilogue) -----
__global__ void __launch_bounds__(256)
gather2_kernel(const float* __restrict__ b2, float* __restrict__ out, int N) {
    int tid = threadIdx.x;
    int node = blockIdx.x * 8 + (tid >> 5);
    int lane = tid & 31;
    if (node >= N) return;
    int beg = off2_final(node);
    int nxt = node + 1;
    int end = (nxt == N) ? g_off2[N] : off2_final(nxt);
    float2 acc = make_float2(0.f, 0.f);
    const float2* H = reinterpret_cast<const float2*>(g_HG2);
    int j = beg;
    for (; j + 4 <= end; j += 4) {
        int s0 = g_csr2[j], s1 = g_csr2[j + 1];
        int s2 = g_csr2[j + 2], s3 = g_csr2[j + 3];
        float w0 = g_dinv2[s0], w1 = g_dinv2[s1];
        float w2 = g_dinv2[s2], w3 = g_dinv2[s3];
        float2 v0 = H[(size_t)s0 * 32 + lane];
        float2 v1 = H[(size_t)s1 * 32 + lane];
        float2 v2 = H[(size_t)s2 * 32 + lane];
        float2 v3 = H[(size_t)s3 * 32 + lane];
        acc.x += w0 * v0.x + w1 * v1.x + w2 * v2.x + w3 * v3.x;
        acc.y += w0 * v0.y + w1 * v1.y + w2 * v2.y + w3 * v3.y;
    }
    for (; j < end; ++j) {
        int s = g_csr2[j];
        float w = g_dinv2[s];
        float2 v = H[(size_t)s * 32 + lane];
        acc.x += w * v.x; acc.y += w * v.y;
    }
    float di = g_dinv2[node];
    float2 h  = H[(size_t)node * 32 + lane];
    float2 bb = reinterpret_cast<const float2*>(b2)[lane];
    float2 v;
    v.x = di * acc.x + di * di * h.x + bb.x;
    v.y = di * acc.y + di * di * h.y + bb.y;
    reinterpret_cast<float2*>(out)[(size_t)node * 32 + lane] = v;
}

// ---------------- launch -------------------------------------------------------
extern "C" void kernel_launch(void* const* d_in, const int* in_sizes, int n_in,
                              void* d_out, int out_size) {
    const float* x     = (const float*)d_in[0];
    const int*   e1    = (const int*)d_in[1];
    const int*   e2    = (const int*)d_in[2];
    const float* W1    = (const float*)d_in[3];
    const float* b1    = (const float*)d_in[4];
    const float* gamma = (const float*)d_in[5];
    const float* beta  = (const float*)d_in[6];
    const float* W2    = (const float*)d_in[7];
    const float* b2    = (const float*)d_in[8];

    int N = in_sizes[0] / FH;
    int E = in_sizes[1] / 2;

    float* out    = (float*)d_out;            // [N, 64]
    float* hidden = out + (size_t)N * FO;     // [N, 128]

    int nb = (N + SCAN_B - 1) / SCAN_B;
    int gm = (N + 127) / 128;
    int gn = (N + 7) / 8;
    int fillBlocks = (2 * E + 255) / 256;

    // graph prep (scanB fused into scanA's last block; scanC folded into consumers)
    zero_kernel<<<(N + 255) / 256, 256>>>(N);
    deg_kernel<<<(E + 255) / 256, 256>>>(e1, e2, E);
    scanA_kernel<<<dim3(nb, 2), SCAN_B>>>(N);

    // layer 1: GEMM1 (128x128 tile, f32x2) overlapped with CSR fill
    gemm1_fill_kernel<<<gm + fillBlocks, 256>>>(x, W1, N, e1, e2, E, gm);
    gather1_kernel<<<gn, 256>>>(b1, gamma, beta, hidden, N, 1.0f / (float)N);

    // layer 2 (BN + ReLU fused into GEMM2 operand load)
    gemm2_kernel<<<gm, 256>>>(hidden, W2, N);
    gather2_kernel<<<gn, 256>>>(b2, out, N);
}

// round 17
// speedup vs baseline: 1.0831x; 1.0831x over previous
#include <cuda_runtime.h>

#define FH 128
#define FO 64
#define NMAX 50048
#define EMAX 800000
#define SCAN_B 1024
#define NBLK ((NMAX + SCAN_B - 1) / SCAN_B)   // 49

// ---------------- scratch (device globals: no allocation allowed) ------------
__device__ float g_H1[(size_t)NMAX * FH];   // x @ W1
__device__ float g_HG2[(size_t)NMAX * FO];  // bnrelu(hidden) @ W2
__device__ float g_dinv1[NMAX];
__device__ float g_dinv2[NMAX];
__device__ int   g_cnt1[NMAX];
__device__ int   g_cnt2[NMAX];
__device__ int   g_off1[NMAX + 1];  // [i]: block-local exclusive prefix; [N]: total
__device__ int   g_off2[NMAX + 1];
__device__ int   g_pos1[NMAX];
__device__ int   g_pos2[NMAX];
__device__ int   g_csr1[EMAX];
__device__ int   g_csr2[EMAX];
__device__ int   g_bsum[2][NBLK];   // after scanA: exclusive block bases
__device__ float g_sum[FH];
__device__ float g_sumsq[FH];
__device__ float g_scale[FH];
__device__ float g_shift[FH];
__device__ int   g_doneA;
__device__ int   g_done1;

// ---------------- packed f32x2 helpers (sm_100+) ------------------------------
__device__ __forceinline__ unsigned long long pack2(float lo, float hi) {
    unsigned long long r;
    asm("mov.b64 %0, {%1, %2};" : "=l"(r) : "f"(lo), "f"(hi));
    return r;
}
__device__ __forceinline__ void fma2(unsigned long long& d, unsigned long long a,
                                     unsigned long long b) {
    asm("fma.rn.f32x2 %0, %1, %2, %0;" : "+l"(d) : "l"(a), "l"(b));
}
__device__ __forceinline__ void unpack2(unsigned long long u, float& lo, float& hi) {
    asm("mov.b64 {%0, %1}, %2;" : "=f"(lo), "=f"(hi) : "l"(u));
}

// ---------------- zero counters ------------------------------------------------
__global__ void zero_kernel(int N) {
    int i = blockIdx.x * blockDim.x + threadIdx.x;
    if (i < N) { g_cnt1[i] = 0; g_cnt2[i] = 0; g_pos1[i] = 0; g_pos2[i] = 0; }
    if (i < FH) { g_sum[i] = 0.f; g_sumsq[i] = 0.f; }
    if (i == 0) { g_doneA = 0; g_done1 = 0; }
}

// ---------------- degree count (dst side, both graphs) -------------------------
__global__ void deg_kernel(const int* __restrict__ e1,
                           const int* __restrict__ e2, int E) {
    int i = blockIdx.x * blockDim.x + threadIdx.x;
    if (i < E) {
        atomicAdd(&g_cnt1[e1[E + i]], 1);
        atomicAdd(&g_cnt2[e2[E + i]], 1);
    }
}

// ---------------- scan A: per-block scan + totals + dinv; last block scans totals
__global__ void __launch_bounds__(SCAN_B) scanA_kernel(int N) {
    const int* cnt  = blockIdx.y ? g_cnt2  : g_cnt1;
    int*       off  = blockIdx.y ? g_off2  : g_off1;
    float*     dinv = blockIdx.y ? g_dinv2 : g_dinv1;
    __shared__ int sh[SCAN_B];
    __shared__ int isLast;
    int t = threadIdx.x;
    int i = blockIdx.x * SCAN_B + t;
    int v = (i < N) ? cnt[i] : 0;
    if (i < N) dinv[i] = rsqrtf((float)v + 1.0f);  // +1 = self loop
    sh[t] = v;
    __syncthreads();
#pragma unroll
    for (int d = 1; d < SCAN_B; d <<= 1) {
        int u = (t >= d) ? sh[t - d] : 0;
        __syncthreads();
        sh[t] += u;
        __syncthreads();
    }
    if (i < N) off[i] = sh[t] - v;  // block-local exclusive prefix
    if (t == SCAN_B - 1) g_bsum[blockIdx.y][blockIdx.x] = sh[t];

    // ---- fused phase B: last block scans the per-block totals -> bases ----
    __threadfence();
    __syncthreads();
    if (t == 0)
        isLast = (atomicAdd(&g_doneA, 1) == (int)(gridDim.x * gridDim.y) - 1);
    __syncthreads();
    if (!isLast) return;
    int nbv = gridDim.x;
    int g = t >> 6, j = t & 63;  // 128 threads active, 64 per graph
    int bv = 0;
    if (t < 128) { bv = (j < nbv) ? g_bsum[g][j] : 0; sh[t] = bv; }
    __syncthreads();
#pragma unroll
    for (int d = 1; d < 64; d <<= 1) {
        int u = 0;
        if (t < 128 && j >= d) u = sh[t - d];
        __syncthreads();
        if (t < 128) sh[t] += u;
        __syncthreads();
    }
    if (t < 128 && j < nbv) g_bsum[g][j] = sh[t] - bv;  // exclusive bases
    if (t < 128 && j == 63) {
        if (g == 0) g_off1[N] = sh[t]; else g_off2[N] = sh[t];
    }
}

// final offset helpers (off[] is block-local; bsum holds bases)
__device__ __forceinline__ int off1_final(int i) {
    return g_off1[i] + g_bsum[0][i >> 10];
}
__device__ __forceinline__ int off2_final(int i) {
    return g_off2[i] + g_bsum[1][i >> 10];
}

// ---------------- merged GEMM1 (f32x2, 128x64 tile) + CSR fill -----------------
// Blocks [0, 2*gm): g_H1 tile = X @ W1 (BM=128, BN=64, BK=32, f32x2 acc).
// Blocks [2*gm, ..): CSR fill for both graphs (adds scan bases inline).
__global__ void __launch_bounds__(256)
gemm1_fill_kernel(const float* __restrict__ X, const float* __restrict__ W,
                  int N, const int* __restrict__ e1, const int* __restrict__ e2,
                  int E, int gm) {
    __shared__ float XsT[32][132];
    __shared__ float Ws[32][68];
    const int tid = threadIdx.x;

    if ((int)blockIdx.x >= 2 * gm) {
        // ---- CSR fill part ----
        int i = (blockIdx.x - 2 * gm) * 256 + tid;
        if (i < E) {
            int s = e1[i], d = e1[E + i];
            int slot = atomicAdd(&g_pos1[d], 1);
            g_csr1[off1_final(d) + slot] = s;
        } else if (i < 2 * E) {
            int j = i - E;
            int s = e2[j], d = e2[E + j];
            int slot = atomicAdd(&g_pos2[d], 1);
            g_csr2[off2_final(d) + slot] = s;
        }
        return;
    }

    // ---- GEMM part ----
    const int row0 = (blockIdx.x % gm) * 128;
    const int col0 = (blockIdx.x / gm) * 64;
    const int tx   = tid & 15;
    const int ty   = tid >> 4;

    unsigned long long acc[4][4];  // [M row-pair][col], f32x2 {row 2p, 2p+1}
#pragma unroll
    for (int p = 0; p < 4; p++)
#pragma unroll
        for (int j = 0; j < 4; j++) acc[p][j] = 0ull;

    for (int kc = 0; kc < FH; kc += 32) {
        __syncthreads();
        for (int i = tid; i < 1024; i += 256) {
            int r = i >> 3, c4 = i & 7;
            int row = row0 + r;
            float4 v = make_float4(0.f, 0.f, 0.f, 0.f);
            if (row < N)
                v = reinterpret_cast<const float4*>(X + (size_t)row * FH + kc)[c4];
            int k0 = c4 * 4;
            XsT[k0 + 0][r] = v.x;
            XsT[k0 + 1][r] = v.y;
            XsT[k0 + 2][r] = v.z;
            XsT[k0 + 3][r] = v.w;
        }
        for (int i = tid; i < 512; i += 256) {
            int k = i >> 4, c4 = i & 15;
            reinterpret_cast<float4*>(&Ws[k][0])[c4] =
                reinterpret_cast<const float4*>(W + (size_t)(kc + k) * FH + col0)[c4];
        }
        __syncthreads();

#pragma unroll
        for (int k = 0; k < 32; ++k) {
            union { float4 f; unsigned long long u[2]; } A0, A1;
            A0.f = *reinterpret_cast<const float4*>(&XsT[k][ty * 8]);
            A1.f = *reinterpret_cast<const float4*>(&XsT[k][ty * 8 + 4]);
            unsigned long long av[4] = {A0.u[0], A0.u[1], A1.u[0], A1.u[1]};
            float4 b = *reinterpret_cast<const float4*>(&Ws[k][tx * 4]);
            unsigned long long bd[4] = {pack2(b.x, b.x), pack2(b.y, b.y),
                                        pack2(b.z, b.z), pack2(b.w, b.w)};
#pragma unroll
            for (int p = 0; p < 4; p++)
#pragma unroll
                for (int j = 0; j < 4; j++) fma2(acc[p][j], av[p], bd[j]);
        }
    }

#pragma unroll
    for (int p = 0; p < 4; p++) {
        int r0 = row0 + ty * 8 + 2 * p;
        float lo[4], hi[4];
#pragma unroll
        for (int j = 0; j < 4; j++) unpack2(acc[p][j], lo[j], hi[j]);
        if (r0 < N)
            *reinterpret_cast<float4*>(&g_H1[(size_t)r0 * FH + col0 + tx * 4]) =
                make_float4(lo[0], lo[1], lo[2], lo[3]);
        if (r0 + 1 < N)
            *reinterpret_cast<float4*>(&g_H1[(size_t)(r0 + 1) * FH + col0 + tx * 4]) =
                make_float4(hi[0], hi[1], hi[2], hi[3]);
    }
}

// ---------------- GEMM2 (f32x2): g_HG2 = bnrelu(hidden) @ W2 -------------------
__global__ void __launch_bounds__(256)
gemm2_kernel(const float* __restrict__ X, const float* __restrict__ W, int N) {
    __shared__ float XsT[32][132];
    __shared__ float Ws[32][68];

    const int row0 = blockIdx.x * 128;
    const int tid  = threadIdx.x;
    const int tx   = tid & 15;
    const int ty   = tid >> 4;

    unsigned long long acc[4][4];
#pragma unroll
    for (int p = 0; p < 4; p++)
#pragma unroll
        for (int j = 0; j < 4; j++) acc[p][j] = 0ull;

    for (int kc = 0; kc < FH; kc += 32) {
        __syncthreads();
        for (int i = tid; i < 1024; i += 256) {
            int r = i >> 3, c4 = i & 7;
            int row = row0 + r;
            float4 v = make_float4(0.f, 0.f, 0.f, 0.f);
            if (row < N)
                v = reinterpret_cast<const float4*>(X + (size_t)row * FH + kc)[c4];
            int k0 = c4 * 4;
            int g = kc + k0;
            v.x = fmaxf(fmaf(v.x, g_scale[g + 0], g_shift[g + 0]), 0.f);
            v.y = fmaxf(fmaf(v.y, g_scale[g + 1], g_shift[g + 1]), 0.f);
            v.z = fmaxf(fmaf(v.z, g_scale[g + 2], g_shift[g + 2]), 0.f);
            v.w = fmaxf(fmaf(v.w, g_scale[g + 3], g_shift[g + 3]), 0.f);
            XsT[k0 + 0][r] = v.x;
            XsT[k0 + 1][r] = v.y;
            XsT[k0 + 2][r] = v.z;
            XsT[k0 + 3][r] = v.w;
        }
        for (int i = tid; i < 512; i += 256) {
            int k = i >> 4, c4 = i & 15;
            reinterpret_cast<float4*>(&Ws[k][0])[c4] =
                reinterpret_cast<const float4*>(W + (size_t)(kc + k) * FO)[c4];
        }
        __syncthreads();

#pragma unroll
        for (int k = 0; k < 32; ++k) {
            union { float4 f; unsigned long long u[2]; } A0, A1;
            A0.f = *reinterpret_cast<const float4*>(&XsT[k][ty * 8]);
            A1.f = *reinterpret_cast<const float4*>(&XsT[k][ty * 8 + 4]);
            unsigned long long av[4] = {A0.u[0], A0.u[1], A1.u[0], A1.u[1]};
            float4 b = *reinterpret_cast<const float4*>(&Ws[k][tx * 4]);
            unsigned long long bd[4] = {pack2(b.x, b.x), pack2(b.y, b.y),
                                        pack2(b.z, b.z), pack2(b.w, b.w)};
#pragma unroll
            for (int p = 0; p < 4; p++)
#pragma unroll
                for (int j = 0; j < 4; j++) fma2(acc[p][j], av[p], bd[j]);
        }
    }

#pragma unroll
    for (int p = 0; p < 4; p++) {
        int r0 = row0 + ty * 8 + 2 * p;
        float lo[4], hi[4];
#pragma unroll
        for (int j = 0; j < 4; j++) unpack2(acc[p][j], lo[j], hi[j]);
        if (r0 < N)
            *reinterpret_cast<float4*>(&g_HG2[(size_t)r0 * FO + tx * 4]) =
                make_float4(lo[0], lo[1], lo[2], lo[3]);
        if (r0 + 1 < N)
            *reinterpret_cast<float4*>(&g_HG2[(size_t)(r0 + 1) * FO + tx * 4]) =
                make_float4(hi[0], hi[1], hi[2], hi[3]);
    }
}

// ---------------- gather layer 1 (fused bias+selfloop+BN stats+BN prep) --------
__global__ void __launch_bounds__(256)
gather1_kernel(const float* __restrict__ b1, const float* __restrict__ gamma,
               const float* __restrict__ beta, float* __restrict__ hidden,
               int N, float invN) {
    __shared__ float s_s[FH], s_q[FH];
    __shared__ int isLast;
    int tid = threadIdx.x;
    if (tid < FH) { s_s[tid] = 0.f; s_q[tid] = 0.f; }
    __syncthreads();

    int node = blockIdx.x * 8 + (tid >> 5);
    int lane = tid & 31;
    if (node < N) {
        int beg = off1_final(node);
        int nxt = node + 1;
        int end = (nxt == N) ? g_off1[N] : off1_final(nxt);
        float4 acc = make_float4(0.f, 0.f, 0.f, 0.f);
        const float4* H = reinterpret_cast<const float4*>(g_H1);
        int j = beg;
        for (; j + 4 <= end; j += 4) {
            int s0 = g_csr1[j], s1 = g_csr1[j + 1];
            int s2 = g_csr1[j + 2], s3 = g_csr1[j + 3];
            float w0 = g_dinv1[s0], w1 = g_dinv1[s1];
            float w2 = g_dinv1[s2], w3 = g_dinv1[s3];
            float4 v0 = H[(size_t)s0 * 32 + lane];
            float4 v1 = H[(size_t)s1 * 32 + lane];
            float4 v2 = H[(size_t)s2 * 32 + lane];
            float4 v3 = H[(size_t)s3 * 32 + lane];
            acc.x += w0 * v0.x + w1 * v1.x + w2 * v2.x + w3 * v3.x;
            acc.y += w0 * v0.y + w1 * v1.y + w2 * v2.y + w3 * v3.y;
            acc.z += w0 * v0.z + w1 * v1.z + w2 * v2.z + w3 * v3.z;
            acc.w += w0 * v0.w + w1 * v1.w + w2 * v2.w + w3 * v3.w;
        }
        for (; j < end; ++j) {
            int s = g_csr1[j];
            float w = g_dinv1[s];
            float4 v = H[(size_t)s * 32 + lane];
            acc.x += w * v.x; acc.y += w * v.y;
            acc.z += w * v.z; acc.w += w * v.w;
        }
        float di = g_dinv1[node];
        float4 h  = H[(size_t)node * 32 + lane];
        float4 bb = reinterpret_cast<const float4*>(b1)[lane];
        float4 v;
        v.x = di * acc.x + di * di * h.x + bb.x;
        v.y = di * acc.y + di * di * h.y + bb.y;
        v.z = di * acc.z + di * di * h.z + bb.z;
        v.w = di * acc.w + di * di * h.w + bb.w;
        reinterpret_cast<float4*>(hidden)[(size_t)node * 32 + lane] = v;
        int f = lane * 4;
        atomicAdd(&s_s[f + 0], v.x); atomicAdd(&s_q[f + 0], v.x * v.x);
        atomicAdd(&s_s[f + 1], v.y); atomicAdd(&s_q[f + 1], v.y * v.y);
        atomicAdd(&s_s[f + 2], v.z); atomicAdd(&s_q[f + 2], v.z * v.z);
        atomicAdd(&s_s[f + 3], v.w); atomicAdd(&s_q[f + 3], v.w * v.w);
    }
    __syncthreads();
    if (tid < FH) {
        atomicAdd(&g_sum[tid], s_s[tid]);
        atomicAdd(&g_sumsq[tid], s_q[tid]);
    }
    __threadfence();
    __syncthreads();
    if (tid == 0) isLast = (atomicAdd(&g_done1, 1) == (int)gridDim.x - 1);
    __syncthreads();
    if (isLast && tid < FH) {  // fused BN scale/shift
        float mean = g_sum[tid] * invN;
        float var  = g_sumsq[tid] * invN - mean * mean;
        float sc = gamma[tid] * rsqrtf(var + 1e-5f);
        g_scale[tid] = sc;
        g_shift[tid] = beta[tid] - mean * sc;
    }
}

// ---------------- gather layer 2 (warp/node, float2 lanes, fused epilogue) -----
__global__ void __launch_bounds__(256)
gather2_kernel(const float* __restrict__ b2, float* __restrict__ out, int N) {
    int tid = threadIdx.x;
    int node = blockIdx.x * 8 + (tid >> 5);
    int lane = tid & 31;
    if (node >= N) return;
    int beg = off2_final(node);
    int nxt = node + 1;
    int end = (nxt == N) ? g_off2[N] : off2_final(nxt);
    float2 acc = make_float2(0.f, 0.f);
    const float2* H = reinterpret_cast<const float2*>(g_HG2);
    int j = beg;
    for (; j + 4 <= end; j += 4) {
        int s0 = g_csr2[j], s1 = g_csr2[j + 1];
        int s2 = g_csr2[j + 2], s3 = g_csr2[j + 3];
        float w0 = g_dinv2[s0], w1 = g_dinv2[s1];
        float w2 = g_dinv2[s2], w3 = g_dinv2[s3];
        float2 v0 = H[(size_t)s0 * 32 + lane];
        float2 v1 = H[(size_t)s1 * 32 + lane];
        float2 v2 = H[(size_t)s2 * 32 + lane];
        float2 v3 = H[(size_t)s3 * 32 + lane];
        acc.x += w0 * v0.x + w1 * v1.x + w2 * v2.x + w3 * v3.x;
        acc.y += w0 * v0.y + w1 * v1.y + w2 * v2.y + w3 * v3.y;
    }
    for (; j < end; ++j) {
        int s = g_csr2[j];
        float w = g_dinv2[s];
        float2 v = H[(size_t)s * 32 + lane];
        acc.x += w * v.x; acc.y += w * v.y;
    }
    float di = g_dinv2[node];
    float2 h  = H[(size_t)node * 32 + lane];
    float2 bb = reinterpret_cast<const float2*>(b2)[lane];
    float2 v;
    v.x = di * acc.x + di * di * h.x + bb.x;
    v.y = di * acc.y + di * di * h.y + bb.y;
    reinterpret_cast<float2*>(out)[(size_t)node * 32 + lane] = v;
}

// ---------------- launch -------------------------------------------------------
extern "C" void kernel_launch(void* const* d_in, const int* in_sizes, int n_in,
                              void* d_out, int out_size) {
    const float* x     = (const float*)d_in[0];
    const int*   e1    = (const int*)d_in[1];
    const int*   e2    = (const int*)d_in[2];
    const float* W1    = (const float*)d_in[3];
    const float* b1    = (const float*)d_in[4];
    const float* gamma = (const float*)d_in[5];
    const float* beta  = (const float*)d_in[6];
    const float* W2    = (const float*)d_in[7];
    const float* b2    = (const float*)d_in[8];

    int N = in_sizes[0] / FH;
    int E = in_sizes[1] / 2;

    float* out    = (float*)d_out;            // [N, 64]
    float* hidden = out + (size_t)N * FO;     // [N, 128]

    int nb = (N + SCAN_B - 1) / SCAN_B;
    int gm = (N + 127) / 128;
    int gn = (N + 7) / 8;
    int fillBlocks = (2 * E + 255) / 256;

    // graph prep (scanB fused into scanA's last block; scanC folded into consumers)
    zero_kernel<<<(N + 255) / 256, 256>>>(N);
    deg_kernel<<<(E + 255) / 256, 256>>>(e1, e2, E);
    scanA_kernel<<<dim3(nb, 2), SCAN_B>>>(N);

    // layer 1: GEMM1 (128x64 tile, f32x2) overlapped with CSR fill
    gemm1_fill_kernel<<<2 * gm + fillBlocks, 256>>>(x, W1, N, e1, e2, E, gm);
    gather1_kernel<<<gn, 256>>>(b1, gamma, beta, hidden, N, 1.0f / (float)N);

    // layer 2 (BN + ReLU fused into GEMM2 operand load)
    gemm2_kernel<<<gm, 256>>>(hidden, W2, N);
    gather2_kernel<<<gn, 256>>>(b2, out, N);
}